// round 10
// baseline (speedup 1.0000x reference)
#include <cuda_runtime.h>
#include <cuda_bf16.h>

#define NB     512
#define GLO    (-6.0f)
#define BW     (12.0f / NB)
#define INVW   (NB / 12.0f)
#define MAXB   4
#define MAXPTS 8192
#define MAXPR  (MAXPTS / 2)
#define FULLM  0xFFFFFFFFu
#define STEP   4
#define WIN    512     // rank window half-width (points)
#define TPB    128

// Static scratch. Pair p of (cl,b): g_pk[cl][b][2p] = {x0,x1,y0,y1},
// g_pk[cl][b][2p+1] = {z0,z1,w0,w1}, w = 0.5*||p||^2. x-bin sorted.
__device__ int    g_start[2][MAXB][NB + 1];
__device__ float4 g_pk[2][MAXB][2 * MAXPR];

__device__ __forceinline__ int binOf(float x) {
    int c = (int)floorf((x - GLO) * INVW);
    return min(max(c, 0), NB - 1);
}

// ---- packed f32x2 helpers ----
__device__ __forceinline__ unsigned long long pk2(float lo, float hi) {
    unsigned long long v;
    asm("mov.b64 %0, {%1, %2};" : "=l"(v) : "f"(lo), "f"(hi));
    return v;
}
__device__ __forceinline__ unsigned long long fma2(unsigned long long a,
                                                   unsigned long long b,
                                                   unsigned long long c) {
    unsigned long long d;
    asm("fma.rn.f32x2 %0, %1, %2, %3;" : "=l"(d) : "l"(a), "l"(b), "l"(c));
    return d;
}
__device__ __forceinline__ void unpk2(unsigned long long v, float& lo, float& hi) {
    asm("mov.b64 {%0, %1}, %2;" : "=f"(lo), "=f"(hi) : "l"(v));
}

// Fused setup: one block per (cloud,batch). smem hist -> smem scan -> scatter.
__global__ __launch_bounds__(1024) void k_setup(
    const float* __restrict__ p1, const float* __restrict__ p2,
    int B, int N, int M, float* __restrict__ out)
{
    const int cl = blockIdx.x / B;
    const int b  = blockIdx.x % B;
    const int n  = cl ? M : N;
    const float* __restrict__ P = cl ? (p2 + (size_t)b * M * 3)
                                     : (p1 + (size_t)b * N * 3);
    __shared__ int hist[NB];
    __shared__ int cur[NB];
    const int t = threadIdx.x;

    if (t < NB) hist[t] = 0;
    __syncthreads();

    float xs[8], ys[8], zs[8];
    int nk = 0;
    for (int idx = t; idx < n; idx += 1024) {
        float x = P[idx * 3 + 0], y = P[idx * 3 + 1], z = P[idx * 3 + 2];
        xs[nk] = x; ys[nk] = y; zs[nk] = z; nk++;
        atomicAdd(&hist[binOf(x)], 1);
    }
    __syncthreads();

    int c = (t < NB) ? hist[t] : 0;
    for (int off = 1; off < NB; off <<= 1) {
        int v = (t < NB && t >= off) ? hist[t - off] : 0;
        __syncthreads();
        if (t < NB) hist[t] += v;
        __syncthreads();
    }
    if (t < NB) {
        int excl = hist[t] - c;
        g_start[cl][b][t] = excl;
        cur[t] = excl;
    }
    if (t == 0) {
        g_start[cl][b][NB] = n;
        if (n & 1) {  // pad the unwritten odd half so it can never win a min
            g_pk[cl][b][2 * (n >> 1) + 1].w = __int_as_float(0x7F800000);
        }
        if (blockIdx.x == 0) out[0] = 0.0f;
    }
    __syncthreads();

    nk = 0;
    for (int idx = t; idx < n; idx += 1024) {
        float x = xs[nk], y = ys[nk], z = zs[nk]; nk++;
        int pos = atomicAdd(&cur[binOf(x)], 1);
        int pr = pos >> 1, hh = pos & 1;
        float* Ap = (float*)&g_pk[cl][b][2 * pr];
        float* Bp = (float*)&g_pk[cl][b][2 * pr + 1];
        Ap[hh] = x;  Ap[2 + hh] = y;
        Bp[hh] = z;  Bp[2 + hh] = 0.5f * (x * x + y * y + z * z);
    }
}

// Largest bin b with st[b] <= target (target in [0, n]).
__device__ __forceinline__ int binFromRank(const int* __restrict__ st, int target) {
    int lo = 0, hi = NB;
#pragma unroll
    for (int it = 0; it < 9; it++) {   // 2^9 = 512 = NB
        int mid = (lo + hi) >> 1;
        if (__ldg(&st[mid]) <= target) lo = mid; else hi = mid;
    }
    return lo;
}

// Exact NN: one contiguous rank-window stream (check-free), single exact
// termination test, then rare chunked expansion for unfinished warps.
__global__ __launch_bounds__(TPB) void k_query(int B, int N, int M,
                                               float invBN, float invBM,
                                               float* __restrict__ out)
{
    const int dir = blockIdx.z;           // 0: p1->p2, 1: p2->p1
    const int b   = blockIdx.y;
    const int nq  = dir ? M : N;
    const int qi  = blockIdx.x * blockDim.x + threadIdx.x;
    const int qic = min(qi, nq - 1);
    const float INFv = __int_as_float(0x7F800000);

    const int qc = dir, rc = 1 - dir;
    const int nr = dir ? N : M;

    float4 qa = g_pk[qc][b][2 * (qic >> 1)];
    float4 qb = g_pk[qc][b][2 * (qic >> 1) + 1];
    const int h = qic & 1;
    const float qx = h ? qa.y : qa.x;
    const float qy = h ? qa.w : qa.z;
    const float qz = h ? qb.y : qb.x;
    const float q2 = 2.0f * (h ? qb.w : qb.z);  // ||q||^2

    const int bq  = binOf(qx);
    const int wb0 = __reduce_min_sync(FULLM, bq);
    const int wb1 = __reduce_max_sync(FULLM, bq);

    const ulonglong2* __restrict__ base = (const ulonglong2*)&g_pk[rc][b][0];
    const int* __restrict__ st = g_start[rc][b];

    const unsigned long long nqx = pk2(-qx, -qx);
    const unsigned long long nqy = pk2(-qy, -qy);
    const unsigned long long nqz = pk2(-qz, -qz);
    float mnA = INFv, mnB = INFv;

    auto scanRange = [&](int s0, int s1) {   // point-index range -> pairs
        int p0 = s0 >> 1, p1 = (s1 + 1) >> 1;
        const ulonglong2* ptr = base + 2 * p0;
#pragma unroll 4
        for (int p = p0; p < p1; p++) {
            ulonglong2 av = __ldg(ptr);       // {x0,x1},{y0,y1}
            ulonglong2 cv = __ldg(ptr + 1);   // {z0,z1},{w0,w1}
            ptr += 2;
            unsigned long long s = fma2(av.x, nqx,
                                   fma2(av.y, nqy,
                                   fma2(cv.x, nqz, cv.y)));
            float lo, hi;
            unpk2(s, lo, hi);
            mnA = fminf(mnA, lo);
            mnB = fminf(mnB, hi);
        }
    };

    // ---- Fast path: bin-snapped rank window, one check-free stream ----
    int rank0 = __ldg(&st[wb0]);
    int rank1 = __ldg(&st[wb1 + 1]);
    int bL = (rank0 > WIN) ? binFromRank(st, rank0 - WIN) : 0;
    int bR = (rank1 + WIN < nr) ? binFromRank(st, rank1 + WIN) : NB - 1;
    scanRange(__ldg(&st[bL]), __ldg(&st[bR + 1]));

    // ---- Exact termination test; slow path only if some lane unfinished ----
    {
        float best = fmaf(2.0f, fminf(mnA, mnB), q2);
        bool doneL = (bL == 0);
        if (!doneL) { float dl = qx - (GLO + bL * BW);       doneL = (dl * dl >= best); }
        bool doneR = (bR == NB - 1);
        if (!doneR) { float dr = (GLO + (bR + 1) * BW) - qx; doneR = (dr * dr >= best); }
        if (!__all_sync(FULLM, doneL && doneR)) {
            for (;;) {
                best = fmaf(2.0f, fminf(mnA, mnB), q2);
                doneL = (bL == 0);
                if (!doneL) { float dl = qx - (GLO + bL * BW);       doneL = (dl * dl >= best); }
                doneR = (bR == NB - 1);
                if (!doneR) { float dr = (GLO + (bR + 1) * BW) - qx; doneR = (dr * dr >= best); }
                if (__all_sync(FULLM, doneL && doneR)) break;
                bool needL = __any_sync(FULLM, !doneL) && (bL > 0);
                bool needR = __any_sync(FULLM, !doneR) && (bR < NB - 1);
                if (needL) {
                    int nb = max(bL - STEP, 0);
                    scanRange(__ldg(&st[nb]), __ldg(&st[bL]));
                    bL = nb;
                }
                if (needR) {
                    int nb = min(bR + STEP, NB - 1);
                    scanRange(__ldg(&st[bR + 1]), __ldg(&st[nb + 1]));
                    bR = nb;
                }
                if (!needL && !needR) break;  // safety (unreachable)
            }
        }
    }

    float dnn = fmaxf(fmaf(2.0f, fminf(mnA, mnB), q2), 0.0f);
    float contrib = (qi < nq) ? dnn * (dir ? invBM : invBN) : 0.0f;

    // Warp sum -> one atomic per warp.
#pragma unroll
    for (int o = 16; o > 0; o >>= 1)
        contrib += __shfl_xor_sync(FULLM, contrib, o);
    if ((threadIdx.x & 31) == 0) atomicAdd(out, contrib);
}

extern "C" void kernel_launch(void* const* d_in, const int* in_sizes, int n_in,
                              void* d_out, int out_size)
{
    const float* p1 = (const float*)d_in[0];
    const float* p2 = (const float*)d_in[1];

    const int B = 4;
    const int N = in_sizes[0] / (B * 3);
    const int M = in_sizes[1] / (B * 3);

    k_setup<<<2 * B, 1024>>>(p1, p2, B, N, M, (float*)d_out);

    const int maxNM = N > M ? N : M;
    dim3 qgrid((maxNM + TPB - 1) / TPB, B, 2);
    k_query<<<qgrid, TPB>>>(B, N, M,
                            1.0f / (float)(B * N), 1.0f / (float)(B * M),
                            (float*)d_out);
}

// round 11
// speedup vs baseline: 2.2849x; 2.2849x over previous
#include <cuda_runtime.h>
#include <cuda_bf16.h>

#define NB     512
#define GLO    (-6.0f)
#define BW     (12.0f / NB)
#define INVW   (NB / 12.0f)
#define MAXB   4
#define MAXPTS 8192
#define MAXPR  (MAXPTS / 2)
#define FULLM  0xFFFFFFFFu
#define STEP   8
#define WIN    768      // rank half-width added around block's home ranks
#define TPB    128
#define SMXP   1024     // max staged pairs (32 KB smem)

// Pair p of (cl,b): g_pk[cl][b][2p] = {x0,x1,y0,y1},
// g_pk[cl][b][2p+1] = {z0,z1,w0,w1}, w = 0.5*||p||^2. x-bin sorted.
__device__ int    g_start[2][MAXB][NB + 1];
__device__ float4 g_pk[2][MAXB][2 * MAXPR];

__device__ __forceinline__ int binOf(float x) {
    int c = (int)floorf((x - GLO) * INVW);
    return min(max(c, 0), NB - 1);
}

// ---- packed f32x2 helpers ----
__device__ __forceinline__ unsigned long long pk2(float lo, float hi) {
    unsigned long long v;
    asm("mov.b64 %0, {%1, %2};" : "=l"(v) : "f"(lo), "f"(hi));
    return v;
}
__device__ __forceinline__ unsigned long long fma2(unsigned long long a,
                                                   unsigned long long b,
                                                   unsigned long long c) {
    unsigned long long d;
    asm("fma.rn.f32x2 %0, %1, %2, %3;" : "=l"(d) : "l"(a), "l"(b), "l"(c));
    return d;
}
__device__ __forceinline__ void unpk2(unsigned long long v, float& lo, float& hi) {
    asm("mov.b64 {%0, %1}, %2;" : "=f"(lo), "=f"(hi) : "l"(v));
}

// Fused setup: one block per (cloud,batch). smem hist -> smem scan -> scatter.
__global__ __launch_bounds__(1024) void k_setup(
    const float* __restrict__ p1, const float* __restrict__ p2,
    int B, int N, int M, float* __restrict__ out)
{
    const int cl = blockIdx.x / B;
    const int b  = blockIdx.x % B;
    const int n  = cl ? M : N;
    const float* __restrict__ P = cl ? (p2 + (size_t)b * M * 3)
                                     : (p1 + (size_t)b * N * 3);
    __shared__ int hist[NB];
    __shared__ int cur[NB];
    const int t = threadIdx.x;

    if (t < NB) hist[t] = 0;
    __syncthreads();

    float xs[8], ys[8], zs[8];
    int nk = 0;
    for (int idx = t; idx < n; idx += 1024) {
        float x = P[idx * 3 + 0], y = P[idx * 3 + 1], z = P[idx * 3 + 2];
        xs[nk] = x; ys[nk] = y; zs[nk] = z; nk++;
        atomicAdd(&hist[binOf(x)], 1);
    }
    __syncthreads();

    int c = (t < NB) ? hist[t] : 0;
    for (int off = 1; off < NB; off <<= 1) {
        int v = (t < NB && t >= off) ? hist[t - off] : 0;
        __syncthreads();
        if (t < NB) hist[t] += v;
        __syncthreads();
    }
    if (t < NB) {
        int excl = hist[t] - c;
        g_start[cl][b][t] = excl;
        cur[t] = excl;
    }
    if (t == 0) {
        g_start[cl][b][NB] = n;
        if (n & 1)  // pad the unwritten odd half so it can never win a min
            g_pk[cl][b][2 * (n >> 1) + 1].w = __int_as_float(0x7F800000);
        if (blockIdx.x == 0) out[0] = 0.0f;
    }
    __syncthreads();

    nk = 0;
    for (int idx = t; idx < n; idx += 1024) {
        float x = xs[nk], y = ys[nk], z = zs[nk]; nk++;
        int pos = atomicAdd(&cur[binOf(x)], 1);
        int pr = pos >> 1, hh = pos & 1;
        float* Ap = (float*)&g_pk[cl][b][2 * pr];
        float* Bp = (float*)&g_pk[cl][b][2 * pr + 1];
        Ap[hh] = x;  Ap[2 + hh] = y;
        Bp[hh] = z;  Bp[2 + hh] = 0.5f * (x * x + y * y + z * z);
    }
}

// Largest bin with st[bin] <= target.
__device__ __forceinline__ int binFromRank(const int* __restrict__ st, int target) {
    int lo = 0, hi = NB;
#pragma unroll
    for (int it = 0; it < 9; it++) {
        int mid = (lo + hi) >> 1;
        if (__ldg(&st[mid]) <= target) lo = mid; else hi = mid;
    }
    return lo;
}

__global__ __launch_bounds__(TPB) void k_query(int B, int N, int M,
                                               float invBN, float invBM,
                                               float* __restrict__ out)
{
    __shared__ float4 sPairs[2 * SMXP];   // 32 KB: staged ref pair window

    const int dir = blockIdx.z;           // 0: p1->p2, 1: p2->p1
    const int b   = blockIdx.y;
    const int nq  = dir ? M : N;
    const int nr  = dir ? N : M;
    const int q0  = blockIdx.x * TPB;
    const int qi  = q0 + threadIdx.x;
    const int qic = min(qi, nq - 1);
    const float INFv = __int_as_float(0x7F800000);

    const int qc = dir, rc = 1 - dir;

    // Own query point.
    float4 qa = g_pk[qc][b][2 * (qic >> 1)];
    float4 qb = g_pk[qc][b][2 * (qic >> 1) + 1];
    const int h = qic & 1;
    const float qx = h ? qa.y : qa.x;
    const float qy = h ? qa.w : qa.z;
    const float qz = h ? qb.y : qb.x;
    const float q2 = 2.0f * (h ? qb.w : qb.z);  // ||q||^2

    // Block query x-range (queries are x-sorted): ranks q0 and qe.
    const int qe = min(q0 + TPB, nq) - 1;
    float4 fa = g_pk[qc][b][2 * (q0 >> 1)];
    float qxmin = (q0 & 1) ? fa.y : fa.x;
    float4 la = g_pk[qc][b][2 * (qe >> 1)];
    float qxmax = (qe & 1) ? la.y : la.x;

    const int* __restrict__ st = g_start[rc][b];

    // Bin window covering home ranks +- WIN.
    int rank0 = __ldg(&st[binOf(qxmin)]);
    int rank1 = __ldg(&st[min(binOf(qxmax) + 1, NB)]);
    int bL = (rank0 > WIN) ? binFromRank(st, rank0 - WIN) : 0;
    int bR = (rank1 + WIN < nr) ? binFromRank(st, rank1 + WIN) : NB - 1;

    // Clamp staged pairs to smem capacity (rare; shrink toward home bins).
    int pLo = __ldg(&st[bL]) >> 1;
    int pHi = (__ldg(&st[bR + 1]) + 1) >> 1;
    const int bQL = binOf(qxmin), bQR = binOf(qxmax);
    while (pHi - pLo > SMXP) {
        if (bR > bQR)      { bR--; pHi = (__ldg(&st[bR + 1]) + 1) >> 1; }
        else if (bL < bQL) { bL++; pLo = __ldg(&st[bL]) >> 1; }
        else break;  // degenerate; termination test keeps exactness
    }
    int nPairs = min(pHi - pLo, SMXP);

    // Cooperative stage to smem.
    {
        const float4* __restrict__ src = &g_pk[rc][b][2 * pLo];
        for (int i = threadIdx.x; i < 2 * nPairs; i += TPB)
            sPairs[i] = __ldg(&src[i]);
    }
    __syncthreads();

    const unsigned long long nqx = pk2(-qx, -qx);
    const unsigned long long nqy = pk2(-qy, -qy);
    const unsigned long long nqz = pk2(-qz, -qz);
    float mnA = INFv, mnB = INFv;

    // Main scan from shared memory (brute-force-proven inner loop).
    {
        const ulonglong2* __restrict__ sp = (const ulonglong2*)sPairs;
#pragma unroll 4
        for (int p = 0; p < nPairs; p++) {
            ulonglong2 av = sp[2 * p];       // {x0,x1},{y0,y1}
            ulonglong2 cv = sp[2 * p + 1];   // {z0,z1},{w0,w1}
            unsigned long long s = fma2(av.x, nqx,
                                   fma2(av.y, nqy,
                                   fma2(cv.x, nqz, cv.y)));
            float lo, hi;
            unpk2(s, lo, hi);
            mnA = fminf(mnA, lo);
            mnB = fminf(mnB, hi);
        }
    }

    // Exact termination test; rare gmem slow path for unfinished warps.
    {
        const ulonglong2* __restrict__ base = (const ulonglong2*)&g_pk[rc][b][0];
        float best = fmaf(2.0f, fminf(mnA, mnB), q2);
        bool doneL = (bL == 0);
        if (!doneL) { float dl = qx - (GLO + bL * BW);       doneL = (dl * dl >= best); }
        bool doneR = (bR == NB - 1);
        if (!doneR) { float dr = (GLO + (bR + 1) * BW) - qx; doneR = (dr * dr >= best); }
        if (!__all_sync(FULLM, doneL && doneR)) {
            int cL = bL, cR = bR;
            for (;;) {
                best = fmaf(2.0f, fminf(mnA, mnB), q2);
                doneL = (cL == 0);
                if (!doneL) { float dl = qx - (GLO + cL * BW);       doneL = (dl * dl >= best); }
                doneR = (cR == NB - 1);
                if (!doneR) { float dr = (GLO + (cR + 1) * BW) - qx; doneR = (dr * dr >= best); }
                if (__all_sync(FULLM, doneL && doneR)) break;
                bool needL = __any_sync(FULLM, !doneL) && (cL > 0);
                bool needR = __any_sync(FULLM, !doneR) && (cR < NB - 1);
                if (needL) {
                    int nb = max(cL - STEP, 0);
                    int s0 = __ldg(&st[nb]) >> 1, s1 = (__ldg(&st[cL]) + 1) >> 1;
                    for (int p = s0; p < s1; p++) {
                        ulonglong2 av = __ldg(base + 2 * p);
                        ulonglong2 cv = __ldg(base + 2 * p + 1);
                        unsigned long long s = fma2(av.x, nqx,
                                               fma2(av.y, nqy,
                                               fma2(cv.x, nqz, cv.y)));
                        float lo, hi; unpk2(s, lo, hi);
                        mnA = fminf(mnA, lo); mnB = fminf(mnB, hi);
                    }
                    cL = nb;
                }
                if (needR) {
                    int nb = min(cR + STEP, NB - 1);
                    int s0 = __ldg(&st[cR + 1]) >> 1, s1 = (__ldg(&st[nb + 1]) + 1) >> 1;
                    for (int p = s0; p < s1; p++) {
                        ulonglong2 av = __ldg(base + 2 * p);
                        ulonglong2 cv = __ldg(base + 2 * p + 1);
                        unsigned long long s = fma2(av.x, nqx,
                                               fma2(av.y, nqy,
                                               fma2(cv.x, nqz, cv.y)));
                        float lo, hi; unpk2(s, lo, hi);
                        mnA = fminf(mnA, lo); mnB = fminf(mnB, hi);
                    }
                    cR = nb;
                }
                if (!needL && !needR) break;
            }
        }
    }

    float dnn = fmaxf(fmaf(2.0f, fminf(mnA, mnB), q2), 0.0f);
    float contrib = (qi < nq) ? dnn * (dir ? invBM : invBN) : 0.0f;

#pragma unroll
    for (int o = 16; o > 0; o >>= 1)
        contrib += __shfl_xor_sync(FULLM, contrib, o);
    if ((threadIdx.x & 31) == 0) atomicAdd(out, contrib);
}

extern "C" void kernel_launch(void* const* d_in, const int* in_sizes, int n_in,
                              void* d_out, int out_size)
{
    const float* p1 = (const float*)d_in[0];
    const float* p2 = (const float*)d_in[1];

    const int B = 4;
    const int N = in_sizes[0] / (B * 3);
    const int M = in_sizes[1] / (B * 3);

    k_setup<<<2 * B, 1024>>>(p1, p2, B, N, M, (float*)d_out);

    const int maxNM = N > M ? N : M;
    dim3 qgrid((maxNM + TPB - 1) / TPB, B, 2);
    k_query<<<qgrid, TPB>>>(B, N, M,
                            1.0f / (float)(B * N), 1.0f / (float)(B * M),
                            (float*)d_out);
}

// round 12
// speedup vs baseline: 6.6525x; 2.9115x over previous
#include <cuda_runtime.h>
#include <cuda_bf16.h>

#define NB     512
#define GLO    (-6.0f)
#define BW     (12.0f / NB)
#define INVW   (NB / 12.0f)
#define MAXB   4
#define MAXPTS 8192
#define MAXPR  (MAXPTS / 2)
#define FULLM  0xFFFFFFFFu
#define WIN    768      // rank half-width around block's home ranks
#define TPB    128
#define SMXP   1024     // max staged pairs (32 KB smem)
#define MAXQ   (2 * MAXB * MAXPTS)

// Pair p of (cl,b): g_pk[cl][b][2p] = {x0,x1,y0,y1},
// g_pk[cl][b][2p+1] = {z0,z1,w0,w1}, w = 0.5*||p||^2. x-bin sorted.
__device__ int    g_start[2][MAXB][NB + 1];
__device__ float4 g_pk[2][MAXB][2 * MAXPR];
__device__ int    g_ovfCnt;
__device__ int4   g_ovf[MAXQ];   // {code, s0, s1, pad}

__device__ __forceinline__ int binOf(float x) {
    int c = (int)floorf((x - GLO) * INVW);
    return min(max(c, 0), NB - 1);
}

// ---- packed f32x2 helpers ----
__device__ __forceinline__ unsigned long long pk2(float lo, float hi) {
    unsigned long long v;
    asm("mov.b64 %0, {%1, %2};" : "=l"(v) : "f"(lo), "f"(hi));
    return v;
}
__device__ __forceinline__ unsigned long long fma2(unsigned long long a,
                                                   unsigned long long b,
                                                   unsigned long long c) {
    unsigned long long d;
    asm("fma.rn.f32x2 %0, %1, %2, %3;" : "=l"(d) : "l"(a), "l"(b), "l"(c));
    return d;
}
__device__ __forceinline__ void unpk2(unsigned long long v, float& lo, float& hi) {
    asm("mov.b64 {%0, %1}, %2;" : "=f"(lo), "=f"(hi) : "l"(v));
}

// Fused setup: one block per (cloud,batch). smem hist -> smem scan -> scatter.
__global__ __launch_bounds__(1024) void k_setup(
    const float* __restrict__ p1, const float* __restrict__ p2,
    int B, int N, int M, float* __restrict__ out)
{
    const int cl = blockIdx.x / B;
    const int b  = blockIdx.x % B;
    const int n  = cl ? M : N;
    const float* __restrict__ P = cl ? (p2 + (size_t)b * M * 3)
                                     : (p1 + (size_t)b * N * 3);
    __shared__ int hist[NB];
    __shared__ int cur[NB];
    const int t = threadIdx.x;

    if (t < NB) hist[t] = 0;
    __syncthreads();

    float xs[8], ys[8], zs[8];
    int nk = 0;
    for (int idx = t; idx < n; idx += 1024) {
        float x = P[idx * 3 + 0], y = P[idx * 3 + 1], z = P[idx * 3 + 2];
        xs[nk] = x; ys[nk] = y; zs[nk] = z; nk++;
        atomicAdd(&hist[binOf(x)], 1);
    }
    __syncthreads();

    int c = (t < NB) ? hist[t] : 0;
    for (int off = 1; off < NB; off <<= 1) {
        int v = (t < NB && t >= off) ? hist[t - off] : 0;
        __syncthreads();
        if (t < NB) hist[t] += v;
        __syncthreads();
    }
    if (t < NB) {
        int excl = hist[t] - c;
        g_start[cl][b][t] = excl;
        cur[t] = excl;
    }
    if (t == 0) {
        g_start[cl][b][NB] = n;
        if (n & 1)  // pad the unwritten odd half so it can never win a min
            g_pk[cl][b][2 * (n >> 1) + 1].w = __int_as_float(0x7F800000);
        if (blockIdx.x == 0) { out[0] = 0.0f; g_ovfCnt = 0; }
    }
    __syncthreads();

    nk = 0;
    for (int idx = t; idx < n; idx += 1024) {
        float x = xs[nk], y = ys[nk], z = zs[nk]; nk++;
        int pos = atomicAdd(&cur[binOf(x)], 1);
        int pr = pos >> 1, hh = pos & 1;
        float* Ap = (float*)&g_pk[cl][b][2 * pr];
        float* Bp = (float*)&g_pk[cl][b][2 * pr + 1];
        Ap[hh] = x;  Ap[2 + hh] = y;
        Bp[hh] = z;  Bp[2 + hh] = 0.5f * (x * x + y * y + z * z);
    }
}

// Largest bin with st[bin] <= target.
__device__ __forceinline__ int binFromRank(const int* __restrict__ st, int target) {
    int lo = 0, hi = NB;
#pragma unroll
    for (int it = 0; it < 9; it++) {
        int mid = (lo + hi) >> 1;
        if (__ldg(&st[mid]) <= target) lo = mid; else hi = mid;
    }
    return lo;
}

// Pass 1: uniform smem-window scan; per-lane exact finish test;
// unfinished lanes enqueue an exact self-window for pass 2. No slow path.
__global__ __launch_bounds__(TPB) void k_query(int B, int N, int M,
                                               float invBN, float invBM,
                                               float* __restrict__ out)
{
    __shared__ float4 sPairs[2 * SMXP];   // 32 KB staged ref pair window

    const int dir = blockIdx.z;           // 0: p1->p2, 1: p2->p1
    const int b   = blockIdx.y;
    const int nq  = dir ? M : N;
    const int nr  = dir ? N : M;
    const int q0  = blockIdx.x * TPB;
    const int qi  = q0 + threadIdx.x;
    const int qic = min(qi, nq - 1);
    const float INFv = __int_as_float(0x7F800000);

    const int qc = dir, rc = 1 - dir;

    float4 qa = g_pk[qc][b][2 * (qic >> 1)];
    float4 qb = g_pk[qc][b][2 * (qic >> 1) + 1];
    const int h = qic & 1;
    const float qx = h ? qa.y : qa.x;
    const float qy = h ? qa.w : qa.z;
    const float qz = h ? qb.y : qb.x;
    const float q2 = 2.0f * (h ? qb.w : qb.z);  // ||q||^2

    // Block query x-range (queries are x-sorted).
    const int qe = min(q0 + TPB, nq) - 1;
    float4 fa = g_pk[qc][b][2 * (q0 >> 1)];
    float qxmin = (q0 & 1) ? fa.y : fa.x;
    float4 la = g_pk[qc][b][2 * (qe >> 1)];
    float qxmax = (qe & 1) ? la.y : la.x;

    const int* __restrict__ st = g_start[rc][b];

    int rank0 = __ldg(&st[binOf(qxmin)]);
    int rank1 = __ldg(&st[min(binOf(qxmax) + 1, NB)]);
    int bL = (rank0 > WIN) ? binFromRank(st, rank0 - WIN) : 0;
    int bR = (rank1 + WIN < nr) ? binFromRank(st, rank1 + WIN) : NB - 1;

    int pLo = __ldg(&st[bL]) >> 1;
    int pHi = (__ldg(&st[bR + 1]) + 1) >> 1;
    const int bQL = binOf(qxmin), bQR = binOf(qxmax);
    while (pHi - pLo > SMXP) {   // rare smem clamp; shrink away from home bins
        if (bR > bQR)      { bR--; pHi = (__ldg(&st[bR + 1]) + 1) >> 1; }
        else if (bL < bQL) { bL++; pLo = __ldg(&st[bL]) >> 1; }
        else break;
    }
    int nPairs = min(pHi - pLo, SMXP);

    {   // cooperative stage
        const float4* __restrict__ src = &g_pk[rc][b][2 * pLo];
        for (int i = threadIdx.x; i < 2 * nPairs; i += TPB)
            sPairs[i] = __ldg(&src[i]);
    }
    __syncthreads();

    const unsigned long long nqx = pk2(-qx, -qx);
    const unsigned long long nqy = pk2(-qy, -qy);
    const unsigned long long nqz = pk2(-qz, -qz);
    float mnA = INFv, mnB = INFv;

    {   // proven packed-FFMA2 smem scan
        const ulonglong2* __restrict__ sp = (const ulonglong2*)sPairs;
#pragma unroll 4
        for (int p = 0; p < nPairs; p++) {
            ulonglong2 av = sp[2 * p];
            ulonglong2 cv = sp[2 * p + 1];
            unsigned long long s = fma2(av.x, nqx,
                                   fma2(av.y, nqy,
                                   fma2(cv.x, nqz, cv.y)));
            float lo, hi;
            unpk2(s, lo, hi);
            mnA = fminf(mnA, lo);
            mnB = fminf(mnB, hi);
        }
    }

    // Per-lane exact finish test (no warp coupling).
    float best = fmaf(2.0f, fminf(mnA, mnB), q2);
    float dnn  = fmaxf(best, 0.0f);
    bool doneL = (bL == 0);
    if (!doneL) { float dl = qx - (GLO + bL * BW);       doneL = (dl * dl >= best); }
    bool doneR = (bR == NB - 1);
    if (!doneR) { float dr = (GLO + (bR + 1) * BW) - qx; doneR = (dr * dr >= best); }
    const bool valid = (qi < nq);
    const bool need  = valid && !(doneL && doneR);

    float contrib = (valid && !need) ? dnn * (dir ? invBM : invBN) : 0.0f;
#pragma unroll
    for (int o = 16; o > 0; o >>= 1)
        contrib += __shfl_xor_sync(FULLM, contrib, o);
    if ((threadIdx.x & 31) == 0 && contrib != 0.0f) atomicAdd(out, contrib);

    // Warp-aggregated overflow enqueue with exact self-window.
    unsigned m = __ballot_sync(FULLM, need);
    if (m) {
        int lane = threadIdx.x & 31;
        int leader = __ffs(m) - 1;
        int baseIdx = 0;
        if (lane == leader) baseIdx = atomicAdd(&g_ovfCnt, __popc(m));
        baseIdx = __shfl_sync(FULLM, baseIdx, leader);
        if (need) {
            float r = sqrtf(dnn);   // point achieving `best` lies inside window
            int binLo = binOf(qx - r);
            int binHi = binOf(qx + r);
            int s0 = __ldg(&st[binLo]);
            int s1 = __ldg(&st[binHi + 1]);
            int off = __popc(m & ((1u << lane) - 1));
            int code = qi | (b << 14) | (dir << 16);
            g_ovf[baseIdx + off] = make_int4(code, s0, s1, 0);
        }
    }
}

// Pass 2: one warp per overflow query; lanes stride the pair range.
__global__ __launch_bounds__(256) void k_ovf(int B, int N, int M,
                                             float invBN, float invBM,
                                             float* __restrict__ out)
{
    const int nOvf = g_ovfCnt;
    const int lane = threadIdx.x & 31;
    int w  = (blockIdx.x * blockDim.x + threadIdx.x) >> 5;
    const int nW = (gridDim.x * blockDim.x) >> 5;
    const float INFv = __int_as_float(0x7F800000);

    for (int e = w; e < nOvf; e += nW) {
        int4 ent = g_ovf[e];
        const int code = ent.x;
        const int qic = code & 0x3FFF;
        const int b   = (code >> 14) & 3;
        const int dir = (code >> 16) & 1;
        const int qc = dir, rc = 1 - dir;

        float4 qa = g_pk[qc][b][2 * (qic >> 1)];
        float4 qb = g_pk[qc][b][2 * (qic >> 1) + 1];
        const int h = qic & 1;
        const float qx = h ? qa.y : qa.x;
        const float qy = h ? qa.w : qa.z;
        const float qz = h ? qb.y : qb.x;
        const float q2 = 2.0f * (h ? qb.w : qb.z);

        const unsigned long long nqx = pk2(-qx, -qx);
        const unsigned long long nqy = pk2(-qy, -qy);
        const unsigned long long nqz = pk2(-qz, -qz);
        float mnA = INFv, mnB = INFv;

        const ulonglong2* __restrict__ base = (const ulonglong2*)&g_pk[rc][b][0];
        int p0 = ent.y >> 1, p1 = (ent.z + 1) >> 1;
        for (int p = p0 + lane; p < p1; p += 32) {
            ulonglong2 av = __ldg(base + 2 * p);
            ulonglong2 cv = __ldg(base + 2 * p + 1);
            unsigned long long s = fma2(av.x, nqx,
                                   fma2(av.y, nqy,
                                   fma2(cv.x, nqz, cv.y)));
            float lo, hi;
            unpk2(s, lo, hi);
            mnA = fminf(mnA, lo);
            mnB = fminf(mnB, hi);
        }
        float mn = fminf(mnA, mnB);
#pragma unroll
        for (int o = 16; o > 0; o >>= 1)
            mn = fminf(mn, __shfl_xor_sync(FULLM, mn, o));
        if (lane == 0) {
            float dnn = fmaxf(fmaf(2.0f, mn, q2), 0.0f);
            atomicAdd(out, dnn * (dir ? invBM : invBN));
        }
    }
}

extern "C" void kernel_launch(void* const* d_in, const int* in_sizes, int n_in,
                              void* d_out, int out_size)
{
    const float* p1 = (const float*)d_in[0];
    const float* p2 = (const float*)d_in[1];

    const int B = 4;
    const int N = in_sizes[0] / (B * 3);
    const int M = in_sizes[1] / (B * 3);

    k_setup<<<2 * B, 1024>>>(p1, p2, B, N, M, (float*)d_out);

    const int maxNM = N > M ? N : M;
    dim3 qgrid((maxNM + TPB - 1) / TPB, B, 2);
    k_query<<<qgrid, TPB>>>(B, N, M,
                            1.0f / (float)(B * N), 1.0f / (float)(B * M),
                            (float*)d_out);

    k_ovf<<<296, 256>>>(B, N, M,
                        1.0f / (float)(B * N), 1.0f / (float)(B * M),
                        (float*)d_out);
}

// round 13
// speedup vs baseline: 9.5363x; 1.4335x over previous
#include <cuda_runtime.h>
#include <cuda_bf16.h>

#define NB     512
#define GLO    (-6.0f)
#define BW     (12.0f / NB)
#define INVW   (NB / 12.0f)
#define MAXB   4
#define MAXPTS 8192
#define MAXPR  (MAXPTS / 2)
#define FULLM  0xFFFFFFFFu
#define WIN    768      // rank half-width around block's home ranks
#define TPB    128
#define QPT    2
#define QBLK   (TPB * QPT)   // 256 queries per block
#define SMXP   1024     // max staged pairs (32 KB smem)
#define MAXQ   (2 * MAXB * MAXPTS)

// Pair p of (cl,b): g_pk[cl][b][2p] = {x0,x1,y0,y1},
// g_pk[cl][b][2p+1] = {z0,z1,w0,w1}, w = 0.5*||p||^2. x-bin sorted.
__device__ int    g_cnt[2][MAXB][NB];       // counts -> scatter cursors
__device__ int    g_start[2][MAXB][NB + 1];
__device__ float4 g_pk[2][MAXB][2 * MAXPR];
__device__ int    g_ovfCnt;
__device__ int4   g_ovf[MAXQ];   // {code, s0, s1, pad}

__device__ __forceinline__ int binOf(float x) {
    int c = (int)floorf((x - GLO) * INVW);
    return min(max(c, 0), NB - 1);
}

// ---- packed f32x2 helpers ----
__device__ __forceinline__ unsigned long long pk2(float lo, float hi) {
    unsigned long long v;
    asm("mov.b64 %0, {%1, %2};" : "=l"(v) : "f"(lo), "f"(hi));
    return v;
}
__device__ __forceinline__ unsigned long long fma2(unsigned long long a,
                                                   unsigned long long b,
                                                   unsigned long long c) {
    unsigned long long d;
    asm("fma.rn.f32x2 %0, %1, %2, %3;" : "=l"(d) : "l"(a), "l"(b), "l"(c));
    return d;
}
__device__ __forceinline__ void unpk2(unsigned long long v, float& lo, float& hi) {
    asm("mov.b64 {%0, %1}, %2;" : "=f"(lo), "=f"(hi) : "l"(v));
}

// ---------------- setup (wide-grid, 4 small kernels) ----------------

__global__ void k_zero(float* out) {
    int i = blockIdx.x * blockDim.x + threadIdx.x;
    int* c = &g_cnt[0][0][0];
    if (i < 2 * MAXB * NB) c[i] = 0;
    if (i == 0) { out[0] = 0.0f; g_ovfCnt = 0; }
}

__global__ void k_hist(const float* __restrict__ p1, const float* __restrict__ p2,
                       int B, int N, int M)
{
    int idx = blockIdx.x * blockDim.x + threadIdx.x;
    int tot0 = B * N;
    int cl, b; const float* p;
    if (idx < tot0) {
        cl = 0; b = idx / N; p = p1 + (size_t)idx * 3;
    } else if (idx < tot0 + B * M) {
        int j = idx - tot0;
        cl = 1; b = j / M; p = p2 + (size_t)j * 3;
    } else return;
    atomicAdd(&g_cnt[cl][b][binOf(p[0])], 1);
}

__global__ __launch_bounds__(NB) void k_scan(int B, int N, int M) {
    int cl = blockIdx.x / B, b = blockIdx.x % B;
    int n = cl ? M : N;
    __shared__ int sh[NB];
    int t = threadIdx.x;
    int c = g_cnt[cl][b][t];
    sh[t] = c;
    __syncthreads();
    for (int off = 1; off < NB; off <<= 1) {
        int v = (t >= off) ? sh[t - off] : 0;
        __syncthreads();
        sh[t] += v;
        __syncthreads();
    }
    int excl = sh[t] - c;
    g_start[cl][b][t] = excl;
    g_cnt[cl][b][t] = excl;   // scatter cursor
    if (t == NB - 1) {
        g_start[cl][b][NB] = n;
        if (n & 1)   // pad the unwritten odd half so it can never win a min
            g_pk[cl][b][2 * (n >> 1) + 1].w = __int_as_float(0x7F800000);
    }
}

__global__ void k_scatter(const float* __restrict__ p1, const float* __restrict__ p2,
                          int B, int N, int M)
{
    int idx = blockIdx.x * blockDim.x + threadIdx.x;
    int tot0 = B * N;
    int cl, b; const float* p;
    if (idx < tot0) {
        cl = 0; b = idx / N; p = p1 + (size_t)idx * 3;
    } else if (idx < tot0 + B * M) {
        int j = idx - tot0;
        cl = 1; b = j / M; p = p2 + (size_t)j * 3;
    } else return;
    float x = p[0], y = p[1], z = p[2];
    int pos = atomicAdd(&g_cnt[cl][b][binOf(x)], 1);
    int pr = pos >> 1, hh = pos & 1;
    float* Ap = (float*)&g_pk[cl][b][2 * pr];
    float* Bp = (float*)&g_pk[cl][b][2 * pr + 1];
    Ap[hh] = x;  Ap[2 + hh] = y;
    Bp[hh] = z;  Bp[2 + hh] = 0.5f * (x * x + y * y + z * z);
}

// Largest bin with st[bin] <= target.
__device__ __forceinline__ int binFromRank(const int* __restrict__ st, int target) {
    int lo = 0, hi = NB;
#pragma unroll
    for (int it = 0; it < 9; it++) {
        int mid = (lo + hi) >> 1;
        if (__ldg(&st[mid]) <= target) lo = mid; else hi = mid;
    }
    return lo;
}

// Pass 1: QPT=2 queries/thread over one shared smem window; per-lane exact
// finish test; unfinished queries enqueue an exact self-window for pass 2.
__global__ __launch_bounds__(TPB) void k_query(int B, int N, int M,
                                               float invBN, float invBM,
                                               float* __restrict__ out)
{
    __shared__ float4 sPairs[2 * SMXP];   // 32 KB staged ref pair window

    const int dir = blockIdx.z;           // 0: p1->p2, 1: p2->p1
    const int b   = blockIdx.y;
    const int nq  = dir ? M : N;
    const int nr  = dir ? N : M;
    const int q0  = blockIdx.x * QBLK;
    const float INFv = __int_as_float(0x7F800000);
    const float invW = dir ? invBM : invBN;

    const int qc = dir, rc = 1 - dir;

    int   qidx[QPT];
    float qx[QPT], qy[QPT], qz[QPT], q2[QPT];
#pragma unroll
    for (int j = 0; j < QPT; j++) {
        int qi = q0 + j * TPB + threadIdx.x;
        qidx[j] = qi;
        int qic = min(qi, nq - 1);
        float4 qa = g_pk[qc][b][2 * (qic >> 1)];
        float4 qb = g_pk[qc][b][2 * (qic >> 1) + 1];
        int h = qic & 1;
        qx[j] = h ? qa.y : qa.x;
        qy[j] = h ? qa.w : qa.z;
        qz[j] = h ? qb.y : qb.x;
        q2[j] = 2.0f * (h ? qb.w : qb.z);
    }

    // Block query x-range (queries are x-sorted).
    const int qe = min(q0 + QBLK, nq) - 1;
    float4 fa = g_pk[qc][b][2 * (q0 >> 1)];
    float qxmin = (q0 & 1) ? fa.y : fa.x;
    float4 la = g_pk[qc][b][2 * (qe >> 1)];
    float qxmax = (qe & 1) ? la.y : la.x;

    const int* __restrict__ st = g_start[rc][b];

    int rank0 = __ldg(&st[binOf(qxmin)]);
    int rank1 = __ldg(&st[min(binOf(qxmax) + 1, NB)]);
    int bL = (rank0 > WIN) ? binFromRank(st, rank0 - WIN) : 0;
    int bR = (rank1 + WIN < nr) ? binFromRank(st, rank1 + WIN) : NB - 1;

    int pLo = __ldg(&st[bL]) >> 1;
    int pHi = (__ldg(&st[bR + 1]) + 1) >> 1;
    const int bQL = binOf(qxmin), bQR = binOf(qxmax);
    while (pHi - pLo > SMXP) {   // rare smem clamp; shrink away from home bins
        if (bR > bQR)      { bR--; pHi = (__ldg(&st[bR + 1]) + 1) >> 1; }
        else if (bL < bQL) { bL++; pLo = __ldg(&st[bL]) >> 1; }
        else break;
    }
    int nPairs = min(pHi - pLo, SMXP);

    {   // cooperative stage
        const float4* __restrict__ src = &g_pk[rc][b][2 * pLo];
        for (int i = threadIdx.x; i < 2 * nPairs; i += TPB)
            sPairs[i] = __ldg(&src[i]);
    }
    __syncthreads();

    unsigned long long nqx[QPT], nqy[QPT], nqz[QPT];
    float mnA[QPT], mnB[QPT];
#pragma unroll
    for (int j = 0; j < QPT; j++) {
        nqx[j] = pk2(-qx[j], -qx[j]);
        nqy[j] = pk2(-qy[j], -qy[j]);
        nqz[j] = pk2(-qz[j], -qz[j]);
        mnA[j] = INFv; mnB[j] = INFv;
    }

    {   // packed-FFMA2 smem scan, 2 queries per staged pair
        const ulonglong2* __restrict__ sp = (const ulonglong2*)sPairs;
#pragma unroll 4
        for (int p = 0; p < nPairs; p++) {
            ulonglong2 av = sp[2 * p];
            ulonglong2 cv = sp[2 * p + 1];
#pragma unroll
            for (int j = 0; j < QPT; j++) {
                unsigned long long s = fma2(av.x, nqx[j],
                                       fma2(av.y, nqy[j],
                                       fma2(cv.x, nqz[j], cv.y)));
                float lo, hi;
                unpk2(s, lo, hi);
                mnA[j] = fminf(mnA[j], lo);
                mnB[j] = fminf(mnB[j], hi);
            }
        }
    }

    // Per-query exact finish test, contribution, overflow enqueue.
    const int lane = threadIdx.x & 31;
    float contrib = 0.0f;
    bool  need[QPT];
    float dnn[QPT];
#pragma unroll
    for (int j = 0; j < QPT; j++) {
        float best = fmaf(2.0f, fminf(mnA[j], mnB[j]), q2[j]);
        dnn[j] = fmaxf(best, 0.0f);
        bool doneL = (bL == 0);
        if (!doneL) { float dl = qx[j] - (GLO + bL * BW);       doneL = (dl * dl >= best); }
        bool doneR = (bR == NB - 1);
        if (!doneR) { float dr = (GLO + (bR + 1) * BW) - qx[j]; doneR = (dr * dr >= best); }
        bool valid = (qidx[j] < nq);
        need[j] = valid && !(doneL && doneR);
        if (valid && !need[j]) contrib += dnn[j] * invW;
    }
#pragma unroll
    for (int o = 16; o > 0; o >>= 1)
        contrib += __shfl_xor_sync(FULLM, contrib, o);
    if (lane == 0 && contrib != 0.0f) atomicAdd(out, contrib);

#pragma unroll
    for (int j = 0; j < QPT; j++) {
        unsigned m = __ballot_sync(FULLM, need[j]);
        if (m) {
            int leader = __ffs(m) - 1;
            int baseIdx = 0;
            if (lane == leader) baseIdx = atomicAdd(&g_ovfCnt, __popc(m));
            baseIdx = __shfl_sync(FULLM, baseIdx, leader);
            if (need[j]) {
                float r = sqrtf(dnn[j]);   // bound point lies inside window
                int binLo = binOf(qx[j] - r);
                int binHi = binOf(qx[j] + r);
                int s0 = __ldg(&st[binLo]);
                int s1 = __ldg(&st[binHi + 1]);
                int off = __popc(m & ((1u << lane) - 1));
                int code = qidx[j] | (b << 14) | (dir << 16);
                g_ovf[baseIdx + off] = make_int4(code, s0, s1, 0);
            }
        }
    }
}

// Pass 2: one warp per overflow query; lanes stride the pair range.
__global__ __launch_bounds__(256) void k_ovf(int B, int N, int M,
                                             float invBN, float invBM,
                                             float* __restrict__ out)
{
    const int nOvf = g_ovfCnt;
    const int lane = threadIdx.x & 31;
    int w  = (blockIdx.x * blockDim.x + threadIdx.x) >> 5;
    const int nW = (gridDim.x * blockDim.x) >> 5;
    const float INFv = __int_as_float(0x7F800000);

    for (int e = w; e < nOvf; e += nW) {
        int4 ent = g_ovf[e];
        const int code = ent.x;
        const int qic = code & 0x3FFF;
        const int b   = (code >> 14) & 3;
        const int dir = (code >> 16) & 1;
        const int qc = dir, rc = 1 - dir;

        float4 qa = g_pk[qc][b][2 * (qic >> 1)];
        float4 qb = g_pk[qc][b][2 * (qic >> 1) + 1];
        const int h = qic & 1;
        const float qx = h ? qa.y : qa.x;
        const float qy = h ? qa.w : qa.z;
        const float qz = h ? qb.y : qb.x;
        const float q2 = 2.0f * (h ? qb.w : qb.z);

        const unsigned long long nqx = pk2(-qx, -qx);
        const unsigned long long nqy = pk2(-qy, -qy);
        const unsigned long long nqz = pk2(-qz, -qz);
        float mnA = INFv, mnB = INFv;

        const ulonglong2* __restrict__ base = (const ulonglong2*)&g_pk[rc][b][0];
        int p0 = ent.y >> 1, p1 = (ent.z + 1) >> 1;
        for (int p = p0 + lane; p < p1; p += 32) {
            ulonglong2 av = __ldg(base + 2 * p);
            ulonglong2 cv = __ldg(base + 2 * p + 1);
            unsigned long long s = fma2(av.x, nqx,
                                   fma2(av.y, nqy,
                                   fma2(cv.x, nqz, cv.y)));
            float lo, hi;
            unpk2(s, lo, hi);
            mnA = fminf(mnA, lo);
            mnB = fminf(mnB, hi);
        }
        float mn = fminf(mnA, mnB);
#pragma unroll
        for (int o = 16; o > 0; o >>= 1)
            mn = fminf(mn, __shfl_xor_sync(FULLM, mn, o));
        if (lane == 0) {
            float dnn = fmaxf(fmaf(2.0f, mn, q2), 0.0f);
            atomicAdd(out, dnn * (dir ? invBM : invBN));
        }
    }
}

extern "C" void kernel_launch(void* const* d_in, const int* in_sizes, int n_in,
                              void* d_out, int out_size)
{
    const float* p1 = (const float*)d_in[0];
    const float* p2 = (const float*)d_in[1];

    const int B = 4;
    const int N = in_sizes[0] / (B * 3);
    const int M = in_sizes[1] / (B * 3);

    k_zero<<<(2 * MAXB * NB + 255) / 256, 256>>>((float*)d_out);

    const int totPts = B * (N + M);
    k_hist<<<(totPts + 255) / 256, 256>>>(p1, p2, B, N, M);

    k_scan<<<2 * B, NB>>>(B, N, M);

    k_scatter<<<(totPts + 255) / 256, 256>>>(p1, p2, B, N, M);

    const int maxNM = N > M ? N : M;
    dim3 qgrid((maxNM + QBLK - 1) / QBLK, B, 2);
    k_query<<<qgrid, TPB>>>(B, N, M,
                            1.0f / (float)(B * N), 1.0f / (float)(B * M),
                            (float*)d_out);

    k_ovf<<<296, 256>>>(B, N, M,
                        1.0f / (float)(B * N), 1.0f / (float)(B * M),
                        (float*)d_out);
}

// round 14
// speedup vs baseline: 10.0827x; 1.0573x over previous
#include <cuda_runtime.h>
#include <cuda_bf16.h>

#define NB     512
#define GLO    (-6.0f)
#define BW     (12.0f / NB)
#define INVW   (NB / 12.0f)
#define MAXB   4
#define MAXPTS 8192
#define MAXPR  (MAXPTS / 2)
#define FULLM  0xFFFFFFFFu
#define WIN    512      // rank half-width around block's home ranks
#define TPB    128
#define QPT    2
#define QBLK   (TPB * QPT)   // 256 queries per block
#define SMXP   1024     // max staged pairs (32 KB smem)
#define MAXQ   (2 * MAXB * MAXPTS)

// Pair p of (cl,b): g_pk[cl][b][2p] = {x0,x1,y0,y1},
// g_pk[cl][b][2p+1] = {z0,z1,w0,w1}, w = 0.5*||p||^2. x-bin sorted.
__device__ int    g_cnt[2][MAXB][NB];       // histogram counts
__device__ int    g_start[2][MAXB][NB + 1];
__device__ float4 g_pk[2][MAXB][2 * MAXPR];
__device__ int    g_aux[MAXQ];              // per input point: bin<<16 | rank
__device__ int    g_ovfCnt;
__device__ int4   g_ovf[MAXQ];              // {code, s0, s1, pad}

__device__ __forceinline__ int binOf(float x) {
    int c = (int)floorf((x - GLO) * INVW);
    return min(max(c, 0), NB - 1);
}

// ---- packed f32x2 helpers ----
__device__ __forceinline__ unsigned long long pk2(float lo, float hi) {
    unsigned long long v;
    asm("mov.b64 %0, {%1, %2};" : "=l"(v) : "f"(lo), "f"(hi));
    return v;
}
__device__ __forceinline__ unsigned long long fma2(unsigned long long a,
                                                   unsigned long long b,
                                                   unsigned long long c) {
    unsigned long long d;
    asm("fma.rn.f32x2 %0, %1, %2, %3;" : "=l"(d) : "l"(a), "l"(b), "l"(c));
    return d;
}
__device__ __forceinline__ void unpk2(unsigned long long v, float& lo, float& hi) {
    asm("mov.b64 {%0, %1}, %2;" : "=f"(lo), "=f"(hi) : "l"(v));
}

// ---------------- setup ----------------

__global__ void k_zero(float* out) {
    int i = blockIdx.x * blockDim.x + threadIdx.x;
    int* c = &g_cnt[0][0][0];
    if (i < 2 * MAXB * NB) c[i] = 0;
    if (i == 0) { out[0] = 0.0f; g_ovfCnt = 0; }
}

// Histogram; also records each point's (bin, in-bin rank) for atomic-free scatter.
__global__ void k_hist(const float* __restrict__ p1, const float* __restrict__ p2,
                       int B, int N, int M)
{
    int idx = blockIdx.x * blockDim.x + threadIdx.x;
    int tot0 = B * N;
    int cl, b; const float* p;
    if (idx < tot0) {
        cl = 0; b = idx / N; p = p1 + (size_t)idx * 3;
    } else if (idx < tot0 + B * M) {
        int j = idx - tot0;
        cl = 1; b = j / M; p = p2 + (size_t)j * 3;
    } else return;
    int bin = binOf(p[0]);
    int rank = atomicAdd(&g_cnt[cl][b][bin], 1);
    g_aux[idx] = (bin << 16) | rank;
}

__global__ __launch_bounds__(NB) void k_scan(int B, int N, int M) {
    int cl = blockIdx.x / B, b = blockIdx.x % B;
    int n = cl ? M : N;
    __shared__ int sh[NB];
    int t = threadIdx.x;
    int c = g_cnt[cl][b][t];
    sh[t] = c;
    __syncthreads();
    for (int off = 1; off < NB; off <<= 1) {
        int v = (t >= off) ? sh[t - off] : 0;
        __syncthreads();
        sh[t] += v;
        __syncthreads();
    }
    g_start[cl][b][t] = sh[t] - c;
    if (t == NB - 1) {
        g_start[cl][b][NB] = n;
        if (n & 1)   // pad the unwritten odd half so it can never win a min
            g_pk[cl][b][2 * (n >> 1) + 1].w = __int_as_float(0x7F800000);
    }
}

// Atomic-free scatter using saved (bin, rank).
__global__ void k_scatter(const float* __restrict__ p1, const float* __restrict__ p2,
                          int B, int N, int M)
{
    int idx = blockIdx.x * blockDim.x + threadIdx.x;
    int tot0 = B * N;
    int cl, b; const float* p;
    if (idx < tot0) {
        cl = 0; b = idx / N; p = p1 + (size_t)idx * 3;
    } else if (idx < tot0 + B * M) {
        int j = idx - tot0;
        cl = 1; b = j / M; p = p2 + (size_t)j * 3;
    } else return;
    float x = p[0], y = p[1], z = p[2];
    int aux = g_aux[idx];
    int bin = aux >> 16, rank = aux & 0xFFFF;
    int pos = __ldg(&g_start[cl][b][bin]) + rank;
    int pr = pos >> 1, hh = pos & 1;
    float* Ap = (float*)&g_pk[cl][b][2 * pr];
    float* Bp = (float*)&g_pk[cl][b][2 * pr + 1];
    Ap[hh] = x;  Ap[2 + hh] = y;
    Bp[hh] = z;  Bp[2 + hh] = 0.5f * (x * x + y * y + z * z);
}

// Largest bin with st[bin] <= target.
__device__ __forceinline__ int binFromRank(const int* __restrict__ st, int target) {
    int lo = 0, hi = NB;
#pragma unroll
    for (int it = 0; it < 9; it++) {
        int mid = (lo + hi) >> 1;
        if (__ldg(&st[mid]) <= target) lo = mid; else hi = mid;
    }
    return lo;
}

// Pass 1: QPT=2 queries/thread over one shared smem window; per-lane exact
// finish test; unfinished queries enqueue an exact self-window for pass 2.
__global__ __launch_bounds__(TPB) void k_query(int B, int N, int M,
                                               float invBN, float invBM,
                                               float* __restrict__ out)
{
    __shared__ float4 sPairs[2 * SMXP];   // 32 KB staged ref pair window

    const int dir = blockIdx.z;           // 0: p1->p2, 1: p2->p1
    const int b   = blockIdx.y;
    const int nq  = dir ? M : N;
    const int nr  = dir ? N : M;
    const int q0  = blockIdx.x * QBLK;
    const float INFv = __int_as_float(0x7F800000);
    const float invW = dir ? invBM : invBN;

    const int qc = dir, rc = 1 - dir;

    int   qidx[QPT];
    float qx[QPT], qy[QPT], qz[QPT], q2[QPT];
#pragma unroll
    for (int j = 0; j < QPT; j++) {
        int qi = q0 + j * TPB + threadIdx.x;
        qidx[j] = qi;
        int qic = min(qi, nq - 1);
        float4 qa = g_pk[qc][b][2 * (qic >> 1)];
        float4 qb = g_pk[qc][b][2 * (qic >> 1) + 1];
        int h = qic & 1;
        qx[j] = h ? qa.y : qa.x;
        qy[j] = h ? qa.w : qa.z;
        qz[j] = h ? qb.y : qb.x;
        q2[j] = 2.0f * (h ? qb.w : qb.z);
    }

    // Block query x-range (queries are x-sorted).
    const int qe = min(q0 + QBLK, nq) - 1;
    float4 fa = g_pk[qc][b][2 * (q0 >> 1)];
    float qxmin = (q0 & 1) ? fa.y : fa.x;
    float4 la = g_pk[qc][b][2 * (qe >> 1)];
    float qxmax = (qe & 1) ? la.y : la.x;

    const int* __restrict__ st = g_start[rc][b];

    int rank0 = __ldg(&st[binOf(qxmin)]);
    int rank1 = __ldg(&st[min(binOf(qxmax) + 1, NB)]);
    int bL = (rank0 > WIN) ? binFromRank(st, rank0 - WIN) : 0;
    int bR = (rank1 + WIN < nr) ? binFromRank(st, rank1 + WIN) : NB - 1;

    int pLo = __ldg(&st[bL]) >> 1;
    int pHi = (__ldg(&st[bR + 1]) + 1) >> 1;
    const int bQL = binOf(qxmin), bQR = binOf(qxmax);
    while (pHi - pLo > SMXP) {   // rare smem clamp; shrink away from home bins
        if (bR > bQR)      { bR--; pHi = (__ldg(&st[bR + 1]) + 1) >> 1; }
        else if (bL < bQL) { bL++; pLo = __ldg(&st[bL]) >> 1; }
        else break;
    }
    int nPairs = min(pHi - pLo, SMXP);

    {   // cooperative stage
        const float4* __restrict__ src = &g_pk[rc][b][2 * pLo];
        for (int i = threadIdx.x; i < 2 * nPairs; i += TPB)
            sPairs[i] = __ldg(&src[i]);
    }
    __syncthreads();

    unsigned long long nqx[QPT], nqy[QPT], nqz[QPT];
    float mnA[QPT], mnB[QPT];
#pragma unroll
    for (int j = 0; j < QPT; j++) {
        nqx[j] = pk2(-qx[j], -qx[j]);
        nqy[j] = pk2(-qy[j], -qy[j]);
        nqz[j] = pk2(-qz[j], -qz[j]);
        mnA[j] = INFv; mnB[j] = INFv;
    }

    {   // packed-FFMA2 smem scan, QPT queries per staged pair
        const ulonglong2* __restrict__ sp = (const ulonglong2*)sPairs;
#pragma unroll 4
        for (int p = 0; p < nPairs; p++) {
            ulonglong2 av = sp[2 * p];
            ulonglong2 cv = sp[2 * p + 1];
#pragma unroll
            for (int j = 0; j < QPT; j++) {
                unsigned long long s = fma2(av.x, nqx[j],
                                       fma2(av.y, nqy[j],
                                       fma2(cv.x, nqz[j], cv.y)));
                float lo, hi;
                unpk2(s, lo, hi);
                mnA[j] = fminf(mnA[j], lo);
                mnB[j] = fminf(mnB[j], hi);
            }
        }
    }

    // Per-query exact finish test, contribution, overflow enqueue.
    const int lane = threadIdx.x & 31;
    float contrib = 0.0f;
    bool  need[QPT];
    float dnn[QPT];
#pragma unroll
    for (int j = 0; j < QPT; j++) {
        float best = fmaf(2.0f, fminf(mnA[j], mnB[j]), q2[j]);
        dnn[j] = fmaxf(best, 0.0f);
        bool doneL = (bL == 0);
        if (!doneL) { float dl = qx[j] - (GLO + bL * BW);       doneL = (dl * dl >= best); }
        bool doneR = (bR == NB - 1);
        if (!doneR) { float dr = (GLO + (bR + 1) * BW) - qx[j]; doneR = (dr * dr >= best); }
        bool valid = (qidx[j] < nq);
        need[j] = valid && !(doneL && doneR);
        if (valid && !need[j]) contrib += dnn[j] * invW;
    }
#pragma unroll
    for (int o = 16; o > 0; o >>= 1)
        contrib += __shfl_xor_sync(FULLM, contrib, o);
    if (lane == 0 && contrib != 0.0f) atomicAdd(out, contrib);

#pragma unroll
    for (int j = 0; j < QPT; j++) {
        unsigned m = __ballot_sync(FULLM, need[j]);
        if (m) {
            int leader = __ffs(m) - 1;
            int baseIdx = 0;
            if (lane == leader) baseIdx = atomicAdd(&g_ovfCnt, __popc(m));
            baseIdx = __shfl_sync(FULLM, baseIdx, leader);
            if (need[j]) {
                float r = sqrtf(dnn[j]);   // bound point lies inside window
                int binLo = binOf(qx[j] - r);
                int binHi = binOf(qx[j] + r);
                int s0 = __ldg(&st[binLo]);
                int s1 = __ldg(&st[binHi + 1]);
                int off = __popc(m & ((1u << lane) - 1));
                int code = qidx[j] | (b << 14) | (dir << 16);
                g_ovf[baseIdx + off] = make_int4(code, s0, s1, 0);
            }
        }
    }
}

// Pass 2: one warp per overflow query; lanes stride the pair range.
__global__ __launch_bounds__(256) void k_ovf(int B, int N, int M,
                                             float invBN, float invBM,
                                             float* __restrict__ out)
{
    const int nOvf = g_ovfCnt;
    const int lane = threadIdx.x & 31;
    int w  = (blockIdx.x * blockDim.x + threadIdx.x) >> 5;
    const int nW = (gridDim.x * blockDim.x) >> 5;
    const float INFv = __int_as_float(0x7F800000);

    for (int e = w; e < nOvf; e += nW) {
        int4 ent = g_ovf[e];
        const int code = ent.x;
        const int qic = code & 0x3FFF;
        const int b   = (code >> 14) & 3;
        const int dir = (code >> 16) & 1;
        const int qc = dir, rc = 1 - dir;

        float4 qa = g_pk[qc][b][2 * (qic >> 1)];
        float4 qb = g_pk[qc][b][2 * (qic >> 1) + 1];
        const int h = qic & 1;
        const float qx = h ? qa.y : qa.x;
        const float qy = h ? qa.w : qa.z;
        const float qz = h ? qb.y : qb.x;
        const float q2 = 2.0f * (h ? qb.w : qb.z);

        const unsigned long long nqx = pk2(-qx, -qx);
        const unsigned long long nqy = pk2(-qy, -qy);
        const unsigned long long nqz = pk2(-qz, -qz);
        float mnA = INFv, mnB = INFv;

        const ulonglong2* __restrict__ base = (const ulonglong2*)&g_pk[rc][b][0];
        int p0 = ent.y >> 1, p1 = (ent.z + 1) >> 1;
        for (int p = p0 + lane; p < p1; p += 32) {
            ulonglong2 av = __ldg(base + 2 * p);
            ulonglong2 cv = __ldg(base + 2 * p + 1);
            unsigned long long s = fma2(av.x, nqx,
                                   fma2(av.y, nqy,
                                   fma2(cv.x, nqz, cv.y)));
            float lo, hi;
            unpk2(s, lo, hi);
            mnA = fminf(mnA, lo);
            mnB = fminf(mnB, hi);
        }
        float mn = fminf(mnA, mnB);
#pragma unroll
        for (int o = 16; o > 0; o >>= 1)
            mn = fminf(mn, __shfl_xor_sync(FULLM, mn, o));
        if (lane == 0) {
            float dnn = fmaxf(fmaf(2.0f, mn, q2), 0.0f);
            atomicAdd(out, dnn * (dir ? invBM : invBN));
        }
    }
}

extern "C" void kernel_launch(void* const* d_in, const int* in_sizes, int n_in,
                              void* d_out, int out_size)
{
    const float* p1 = (const float*)d_in[0];
    const float* p2 = (const float*)d_in[1];

    const int B = 4;
    const int N = in_sizes[0] / (B * 3);
    const int M = in_sizes[1] / (B * 3);

    k_zero<<<(2 * MAXB * NB + 255) / 256, 256>>>((float*)d_out);

    const int totPts = B * (N + M);
    k_hist<<<(totPts + 255) / 256, 256>>>(p1, p2, B, N, M);

    k_scan<<<2 * B, NB>>>(B, N, M);

    k_scatter<<<(totPts + 255) / 256, 256>>>(p1, p2, B, N, M);

    const int maxNM = N > M ? N : M;
    dim3 qgrid((maxNM + QBLK - 1) / QBLK, B, 2);
    k_query<<<qgrid, TPB>>>(B, N, M,
                            1.0f / (float)(B * N), 1.0f / (float)(B * M),
                            (float*)d_out);

    k_ovf<<<296, 256>>>(B, N, M,
                        1.0f / (float)(B * N), 1.0f / (float)(B * M),
                        (float*)d_out);
}